// round 1
// baseline (speedup 1.0000x reference)
#include <cuda_runtime.h>
#include <cuda_bf16.h>

#define NB 16
#define CC 256
#define HWP 4096
#define OT 128
#define PT 64
#define KT 16
#define NELEM (NB*CC*HWP)

// ---------------- scratch (static device allocations) ----------------
__device__ float g_g1[NELEM];
__device__ float g_XG[NELEM];
__device__ float g_xlow[NELEM];
__device__ float g_xup[NELEM];
__device__ float g_base[NELEM];
__device__ float g_dw[NELEM];
__device__ float g_xL[NELEM];

__device__ float g_sum[NB*CC];
__device__ float g_sumsq[NB*CC];
__device__ float g_mean[NB*CC];
__device__ float g_cagate[NB*CC];
__device__ float g_sumxlow[NB*CC];
__device__ float g_gate[NB*CC];
__device__ float g_bninv[CC];
__device__ float g_bnsh[CC];
__device__ float g_gmu[NB*16];
__device__ float g_grstd[NB*16];
__device__ float g_s4g[NB*HWP];
__device__ float g_xh[NB*CC*64];
__device__ float g_xw[NB*CC*64];
__device__ float g_sh[NB*CC*64];
__device__ float g_sw[NB*CC*64];

__device__ __forceinline__ float sigm(float x){ return 1.0f/(1.0f+expf(-x)); }

// ---------------- K0: zero the atomic accumulators ----------------
__global__ void k0_zero()
{
    int i = blockIdx.x*256 + threadIdx.x;   // grid covers 65536
    if (i < NB*CC){ g_sum[i]=0.f; g_sumsq[i]=0.f; g_sumxlow[i]=0.f; }
    if (i < NB*HWP) g_s4g[i]=0.f;
}

// ---------------- K1: dual GEMM g1/g2 + XG + fused reductions ----------------
__global__ __launch_bounds__(256) void k1_gemm(
    const float* __restrict__ x1, const float* __restrict__ x2,
    const float* __restrict__ w1, const float* __restrict__ w2,
    const float* __restrict__ b1, const float* __restrict__ b2,
    const float* __restrict__ w4g)
{
    __shared__ float sW1[OT][KT+1];
    __shared__ float sW2[OT][KT+1];
    __shared__ float sA1[KT][PT];
    __shared__ float sA2[KT][PT];
    __shared__ float sred[16][PT];

    const int tid = threadIdx.x;
    const int tx = tid & 15, ty = tid >> 4;
    const int pBase = blockIdx.x * PT;
    const int oBase = blockIdx.y * OT;
    const int n = blockIdx.z;

    const float* A1 = x1 + (size_t)n * CC * HWP;
    const float* A2 = x2 + (size_t)n * CC * HWP;

    float acc1[8][4], acc2[8][4];
    #pragma unroll
    for (int i=0;i<8;i++)
        #pragma unroll
        for (int j=0;j<4;j++){ acc1[i][j]=0.f; acc2[i][j]=0.f; }

    for (int k0 = 0; k0 < CC; k0 += KT){
        #pragma unroll
        for (int r=0;r<2;r++){
            int f = tid + 256*r;
            int oo = f >> 2;
            int kk = (f & 3) << 2;
            const float4 v1 = *(const float4*)(w1 + (size_t)(oBase+oo)*CC + k0 + kk);
            const float4 v2 = *(const float4*)(w2 + (size_t)(oBase+oo)*CC + k0 + kk);
            sW1[oo][kk+0]=v1.x; sW1[oo][kk+1]=v1.y; sW1[oo][kk+2]=v1.z; sW1[oo][kk+3]=v1.w;
            sW2[oo][kk+0]=v2.x; sW2[oo][kk+1]=v2.y; sW2[oo][kk+2]=v2.z; sW2[oo][kk+3]=v2.w;
        }
        {
            int kk = tid >> 4;
            int pp = (tid & 15) << 2;
            *(float4*)&sA1[kk][pp] = *(const float4*)(A1 + (size_t)(k0+kk)*HWP + pBase + pp);
            *(float4*)&sA2[kk][pp] = *(const float4*)(A2 + (size_t)(k0+kk)*HWP + pBase + pp);
        }
        __syncthreads();
        #pragma unroll
        for (int k=0;k<KT;k++){
            float a1[4], a2[4], wr1[8], wr2[8];
            #pragma unroll
            for (int j=0;j<4;j++){ a1[j]=sA1[k][tx+16*j]; a2[j]=sA2[k][tx+16*j]; }
            #pragma unroll
            for (int i=0;i<8;i++){ wr1[i]=sW1[ty+16*i][k]; wr2[i]=sW2[ty+16*i][k]; }
            #pragma unroll
            for (int i=0;i<8;i++)
                #pragma unroll
                for (int j=0;j<4;j++){
                    acc1[i][j] = fmaf(wr1[i], a1[j], acc1[i][j]);
                    acc2[i][j] = fmaf(wr2[i], a2[j], acc2[i][j]);
                }
        }
        __syncthreads();
    }

    // epilogue: biases, write g1/XG, fused reductions
    float sxp[4] = {0.f,0.f,0.f,0.f};   // per-pixel partial of conv4g dot
    const size_t nb = (size_t)n * CC * HWP;
    #pragma unroll
    for (int i=0;i<8;i++){
        int o = oBase + ty + 16*i;
        float bb1 = b1[o], bb2 = b2[o];
        float wg  = w4g[o];
        float ssum = 0.f, ssq = 0.f;
        #pragma unroll
        for (int j=0;j<4;j++){
            int p = pBase + tx + 16*j;
            float g1v = acc1[i][j] + bb1;
            float g2v = acc2[i][j] + bb2;
            float xg  = g1v + g2v;
            size_t idx = nb + (size_t)o*HWP + p;
            g_g1[idx] = g1v;
            g_XG[idx] = xg;
            ssum += xg;
            ssq  = fmaf(xg, xg, ssq);
            sxp[j] = fmaf(wg, xg, sxp[j]);
        }
        #pragma unroll
        for (int d=8; d; d>>=1){
            ssum += __shfl_xor_sync(0xffffffffu, ssum, d);
            ssq  += __shfl_xor_sync(0xffffffffu, ssq,  d);
        }
        if (tx == 0){
            atomicAdd(&g_sum[n*CC+o],   ssum);
            atomicAdd(&g_sumsq[n*CC+o], ssq);
        }
    }
    #pragma unroll
    for (int j=0;j<4;j++) sred[ty][tx+16*j] = sxp[j];
    __syncthreads();
    if (tid < PT){
        float s = 0.f;
        #pragma unroll
        for (int t=0;t<16;t++) s += sred[t][tid];
        atomicAdd(&g_s4g[n*HWP + pBase + tid], s);
    }
}

// ---------------- K2: per-(n,c) stats, channel-att conv1d, group mu/std ----------------
__global__ __launch_bounds__(256) void k2_stats(
    const float* __restrict__ bn_g, const float* __restrict__ bn_b,
    const float* __restrict__ bn_rm, const float* __restrict__ bn_rv,
    const float* __restrict__ ca_w)
{
    const int n = blockIdx.x;
    const int c = threadIdx.x;
    __shared__ float sm[CC];
    float mean = g_sum[n*CC+c] * (1.0f/HWP);
    sm[c] = mean;
    g_mean[n*CC+c] = mean;
    if (n == 0){
        float inv = bn_g[c] * rsqrtf(bn_rv[c] + 1e-5f);
        g_bninv[c] = inv;
        g_bnsh[c]  = bn_b[c] - bn_rm[c]*inv;
    }
    __syncthreads();
    float y = 0.f;
    #pragma unroll
    for (int k=0;k<5;k++){
        int cc2 = c + k - 2;
        if (cc2 >= 0 && cc2 < CC) y = fmaf(sm[cc2], ca_w[k], y);
    }
    g_cagate[n*CC+c] = sigm(y);
    if ((c & 15) == 0){
        float s=0.f, q=0.f;
        for (int t=0;t<16;t++){ s += g_sum[n*CC+c+t]; q += g_sumsq[n*CC+c+t]; }
        const float cnt = 16.0f*HWP;
        float mu  = s / cnt;
        float var = (q - cnt*mu*mu) / (cnt - 1.0f);
        var = fmaxf(var, 0.0f);
        float sd = sqrtf(var);
        g_gmu[n*16 + (c>>4)]   = mu;
        g_grstd[n*16 + (c>>4)] = 1.0f/(sd + 1e-10f);
    }
}

// ---------------- K3: elementwise masks / x_low / x_up / base = x_gui+temp ----------------
__global__ __launch_bounds__(256) void k3_elem(
    const float* __restrict__ gamma, const float* __restrict__ beta,
    const float* __restrict__ b4g)
{
    const int n = blockIdx.z, c = blockIdx.y;
    const int p0 = blockIdx.x*1024 + threadIdx.x*4;
    const size_t off = ((size_t)n*CC + c)*HWP;
    const float mean = g_mean[n*CC+c];
    const float inv = g_bninv[c], shv = g_bnsh[c];
    const int g = c >> 4;
    const float mu = g_gmu[n*16+g], rstd = g_grstd[n*16+g];
    const float gm = gamma[c], bt = beta[c];
    const float cag = g_cagate[n*CC+c];
    const float b4 = b4g[0];

    float4 xg4 = *(const float4*)(g_XG + off + p0);
    float4 g14 = *(const float4*)(g_g1 + off + p0);
    float4 s44 = *(const float4*)(g_s4g + (size_t)n*HWP + p0);
    float4 xl4, xu4, bs4;
    const float* xgp = &xg4.x; const float* g1p = &g14.x; const float* s4p = &s44.x;
    float* xlp = &xl4.x; float* xup = &xu4.x; float* bsp = &bs4.x;
    float lowsum = 0.f;
    #pragma unroll
    for (int l=0;l<4;l++){
        float xg = xgp[l], g1v = g1p[l];
        float g2v = xg - g1v;
        float fu = ((mean >= fmaf(g1v, inv, shv)) ? 1.f : 0.f)
                 + ((mean >= fmaf(g2v, inv, shv)) ? 1.f : 0.f);
        float xu = xg * fu;
        float xl = xg * (2.0f - fu);
        float Xs = xg * sigm(s4p[l] + b4);
        bsp[l] = fmaf((Xs - mu)*rstd, gm, bt) + xg*cag;
        xup[l] = xu; xlp[l] = xl;
        lowsum += xl;
    }
    *(float4*)(g_xlow + off + p0) = xl4;
    *(float4*)(g_xup  + off + p0) = xu4;
    *(float4*)(g_base + off + p0) = bs4;
    #pragma unroll
    for (int d=16; d; d>>=1) lowsum += __shfl_xor_sync(0xffffffffu, lowsum, d);
    __shared__ float wred[8];
    if ((threadIdx.x & 31) == 0) wred[threadIdx.x >> 5] = lowsum;
    __syncthreads();
    if (threadIdx.x == 0){
        float s = 0.f;
        #pragma unroll
        for (int i=0;i<8;i++) s += wred[i];
        atomicAdd(&g_sumxlow[n*CC+c], s);
    }
}

// ---------------- K3.5: gate = softmax(relu(mean(x_low) @ gate_w.T + b)) ----------------
__global__ __launch_bounds__(256) void k_gate(
    const float* __restrict__ gate_w, const float* __restrict__ gate_b)
{
    const int n = blockIdx.x;
    const int o = threadIdx.x;
    __shared__ float mv[CC];
    __shared__ float red[CC];
    mv[o] = g_sumxlow[n*CC+o] * (1.0f/HWP);
    __syncthreads();
    float acc = gate_b[o];
    #pragma unroll 8
    for (int c2=0;c2<CC;c2++) acc = fmaf(mv[c2], gate_w[(size_t)o*CC + c2], acc);
    acc = fmaxf(acc, 0.0f);
    red[o] = acc; __syncthreads();
    for (int s=128; s; s>>=1){ if (o < s) red[o] = fmaxf(red[o], red[o+s]); __syncthreads(); }
    float m = red[0];
    __syncthreads();
    float e = expf(acc - m);
    red[o] = e; __syncthreads();
    for (int s=128; s; s>>=1){ if (o < s) red[o] += red[o+s]; __syncthreads(); }
    g_gate[n*CC+o] = e / red[0];
}

// ---------------- K4: depthwise 3x3 conv on x_low ----------------
__global__ __launch_bounds__(256) void k_dw(
    const float* __restrict__ dw_w, const float* __restrict__ dw_b)
{
    const int nc = blockIdx.x;
    const int c = nc & (CC-1);
    __shared__ float tile[66*66];
    const size_t off = (size_t)nc * HWP;
    for (int i = threadIdx.x; i < 66*66; i += 256){
        int hh = i/66 - 1, ww = i%66 - 1;
        float v = 0.f;
        if (hh >= 0 && hh < 64 && ww >= 0 && ww < 64) v = g_xlow[off + hh*64 + ww];
        tile[i] = v;
    }
    float wc[9];
    #pragma unroll
    for (int k=0;k<9;k++) wc[k] = dw_w[c*9+k];
    const float bb = dw_b[c];
    __syncthreads();
    for (int p = threadIdx.x; p < HWP; p += 256){
        int h = p >> 6, w = p & 63;
        float acc = bb;
        #pragma unroll
        for (int i=0;i<3;i++)
            #pragma unroll
            for (int j=0;j<3;j++)
                acc = fmaf(tile[(h+i)*66 + (w+j)], wc[i*3+j], acc);
        g_dw[off+p] = acc;
    }
}

// ---------------- K5: dual GEMM xL = gate*conv3(dw) + conv4(x_up) + base ----------------
__global__ __launch_bounds__(256) void k5_gemm(
    const float* __restrict__ w3, const float* __restrict__ w4,
    const float* __restrict__ b3, const float* __restrict__ b4)
{
    __shared__ float sW1[OT][KT+1];
    __shared__ float sW2[OT][KT+1];
    __shared__ float sA1[KT][PT];
    __shared__ float sA2[KT][PT];

    const int tid = threadIdx.x;
    const int tx = tid & 15, ty = tid >> 4;
    const int pBase = blockIdx.x * PT;
    const int oBase = blockIdx.y * OT;
    const int n = blockIdx.z;

    const float* A1 = g_dw  + (size_t)n * CC * HWP;
    const float* A2 = g_xup + (size_t)n * CC * HWP;

    float acc1[8][4], acc2[8][4];
    #pragma unroll
    for (int i=0;i<8;i++)
        #pragma unroll
        for (int j=0;j<4;j++){ acc1[i][j]=0.f; acc2[i][j]=0.f; }

    for (int k0 = 0; k0 < CC; k0 += KT){
        #pragma unroll
        for (int r=0;r<2;r++){
            int f = tid + 256*r;
            int oo = f >> 2;
            int kk = (f & 3) << 2;
            const float4 v1 = *(const float4*)(w3 + (size_t)(oBase+oo)*CC + k0 + kk);
            const float4 v2 = *(const float4*)(w4 + (size_t)(oBase+oo)*CC + k0 + kk);
            sW1[oo][kk+0]=v1.x; sW1[oo][kk+1]=v1.y; sW1[oo][kk+2]=v1.z; sW1[oo][kk+3]=v1.w;
            sW2[oo][kk+0]=v2.x; sW2[oo][kk+1]=v2.y; sW2[oo][kk+2]=v2.z; sW2[oo][kk+3]=v2.w;
        }
        {
            int kk = tid >> 4;
            int pp = (tid & 15) << 2;
            *(float4*)&sA1[kk][pp] = *(const float4*)(A1 + (size_t)(k0+kk)*HWP + pBase + pp);
            *(float4*)&sA2[kk][pp] = *(const float4*)(A2 + (size_t)(k0+kk)*HWP + pBase + pp);
        }
        __syncthreads();
        #pragma unroll
        for (int k=0;k<KT;k++){
            float a1[4], a2[4], wr1[8], wr2[8];
            #pragma unroll
            for (int j=0;j<4;j++){ a1[j]=sA1[k][tx+16*j]; a2[j]=sA2[k][tx+16*j]; }
            #pragma unroll
            for (int i=0;i<8;i++){ wr1[i]=sW1[ty+16*i][k]; wr2[i]=sW2[ty+16*i][k]; }
            #pragma unroll
            for (int i=0;i<8;i++)
                #pragma unroll
                for (int j=0;j<4;j++){
                    acc1[i][j] = fmaf(wr1[i], a1[j], acc1[i][j]);
                    acc2[i][j] = fmaf(wr2[i], a2[j], acc2[i][j]);
                }
        }
        __syncthreads();
    }

    const size_t nb = (size_t)n * CC * HWP;
    #pragma unroll
    for (int i=0;i<8;i++){
        int o = oBase + ty + 16*i;
        float bb3 = b3[o], bb4 = b4[o];
        float gt = g_gate[n*CC+o];
        #pragma unroll
        for (int j=0;j<4;j++){
            int p = pBase + tx + 16*j;
            size_t idx = nb + (size_t)o*HWP + p;
            float v = (acc1[i][j] + bb3)*gt + (acc2[i][j] + bb4) + g_base[idx];
            g_xL[idx] = v;
        }
    }
}

// ---------------- K6: row/col means of xL ----------------
__global__ __launch_bounds__(256) void k6_redux()
{
    const int nc = blockIdx.x;
    const size_t off = (size_t)nc * HWP;
    __shared__ float rsum[64];
    __shared__ float cpart[4][64];
    const int tid = threadIdx.x, l = tid & 31, wp = tid >> 5;
    if (tid < 64) rsum[tid] = 0.f;
    __syncthreads();
    const int w = (wp & 1)*32 + l;
    const int hq = wp >> 1;
    float colacc = 0.f;
    for (int r=0;r<16;r++){
        int h = hq*16 + r;
        float v = g_xL[off + h*64 + w];
        colacc += v;
        float s = v;
        #pragma unroll
        for (int d=16; d; d>>=1) s += __shfl_xor_sync(0xffffffffu, s, d);
        if (l == 0) atomicAdd(&rsum[h], s);
    }
    cpart[hq][w] = colacc;
    __syncthreads();
    if (tid < 64){
        g_xw[(size_t)nc*64 + tid] =
            (cpart[0][tid]+cpart[1][tid]+cpart[2][tid]+cpart[3][tid]) * (1.0f/64.0f);
        g_xh[(size_t)nc*64 + tid] = rsum[tid] * (1.0f/64.0f);
    }
}

// ---------------- K7: coordinate attention (tiny GEMMs) ----------------
__global__ __launch_bounds__(256) void k7_latt(
    const float* __restrict__ la1_w,
    const float* __restrict__ la_g, const float* __restrict__ la_b,
    const float* __restrict__ la_rm, const float* __restrict__ la_rv,
    const float* __restrict__ fh_w, const float* __restrict__ fw_w)
{
    const int n = blockIdx.x;
    __shared__ float syc[16][128];
    const int tid = threadIdx.x;
    for (int e = tid; e < 16*128; e += 256){
        int m = e >> 7, l = e & 127;
        const float* src = (l < 64) ? (g_xh + (size_t)n*CC*64 + l)
                                    : (g_xw + (size_t)n*CC*64 + (l - 64));
        float acc = 0.f;
        #pragma unroll 8
        for (int c2=0;c2<CC;c2++) acc = fmaf(la1_w[m*CC + c2], src[(size_t)c2*64], acc);
        float inv = la_g[m] * rsqrtf(la_rv[m] + 1e-5f);
        float v = acc*inv + (la_b[m] - la_rm[m]*inv);
        syc[m][l] = fmaxf(v, 0.f);
    }
    __syncthreads();
    const int c = tid;
    for (int pos=0; pos<64; pos++){
        float sh = 0.f, sw = 0.f;
        #pragma unroll
        for (int m=0;m<16;m++){
            sh = fmaf(fh_w[c*16+m], syc[m][pos],      sh);
            sw = fmaf(fw_w[c*16+m], syc[m][64+pos],   sw);
        }
        g_sh[((size_t)n*CC + c)*64 + pos] = sigm(sh);
        g_sw[((size_t)n*CC + c)*64 + pos] = sigm(sw);
    }
}

// ---------------- K8: final out = xL * sh(h) * sw(w) ----------------
__global__ __launch_bounds__(256) void k8_final(float* __restrict__ out)
{
    const int nc = blockIdx.x;
    __shared__ float shv[64], swv[64];
    const int tid = threadIdx.x;
    if (tid < 64) shv[tid] = g_sh[(size_t)nc*64 + tid];
    else if (tid < 128) swv[tid-64] = g_sw[(size_t)nc*64 + (tid-64)];
    __syncthreads();
    const size_t off = (size_t)nc * HWP;
    for (int f = tid; f < 1024; f += 256){
        int p = f*4;
        int h = p >> 6, w = p & 63;
        float4 v = *(const float4*)(g_xL + off + p);
        float a = shv[h];
        v.x *= a*swv[w+0]; v.y *= a*swv[w+1]; v.z *= a*swv[w+2]; v.w *= a*swv[w+3];
        *(float4*)(out + off + p) = v;
    }
}

// ---------------- launch ----------------
extern "C" void kernel_launch(void* const* d_in, const int* in_sizes, int n_in,
                              void* d_out, int out_size)
{
    const float* x1      = (const float*)d_in[0];
    const float* x2      = (const float*)d_in[1];
    const float* conv1_w = (const float*)d_in[2];
    const float* conv1_b = (const float*)d_in[3];
    const float* conv2_w = (const float*)d_in[4];
    const float* conv2_b = (const float*)d_in[5];
    const float* conv3_w = (const float*)d_in[6];
    const float* conv3_b = (const float*)d_in[7];
    const float* conv4_w = (const float*)d_in[8];
    const float* conv4_b = (const float*)d_in[9];
    const float* conv4g_w= (const float*)d_in[10];
    const float* conv4g_b= (const float*)d_in[11];
    const float* bn_g    = (const float*)d_in[12];
    const float* bn_b    = (const float*)d_in[13];
    const float* bn_rm   = (const float*)d_in[14];
    const float* bn_rv   = (const float*)d_in[15];
    const float* gamma   = (const float*)d_in[16];
    const float* beta    = (const float*)d_in[17];
    const float* gate_w  = (const float*)d_in[18];
    const float* gate_b  = (const float*)d_in[19];
    const float* dw_w    = (const float*)d_in[20];
    const float* dw_b    = (const float*)d_in[21];
    // d_in[22], d_in[23]: interact_w / interact_b — dead code (softmax over size-1 axis == 1)
    const float* ca_w    = (const float*)d_in[24];
    const float* la1_w   = (const float*)d_in[25];
    const float* la_g    = (const float*)d_in[26];
    const float* la_b    = (const float*)d_in[27];
    const float* la_rm   = (const float*)d_in[28];
    const float* la_rv   = (const float*)d_in[29];
    const float* fh_w    = (const float*)d_in[30];
    const float* fw_w    = (const float*)d_in[31];
    float* out = (float*)d_out;

    k0_zero<<<256, 256>>>();
    k1_gemm<<<dim3(HWP/PT, CC/OT, NB), 256>>>(x1, x2, conv1_w, conv2_w, conv1_b, conv2_b, conv4g_w);
    k2_stats<<<NB, CC>>>(bn_g, bn_b, bn_rm, bn_rv, ca_w);
    k3_elem<<<dim3(4, CC, NB), 256>>>(gamma, beta, conv4g_b);
    k_gate<<<NB, CC>>>(gate_w, gate_b);
    k_dw<<<NB*CC, 256>>>(dw_w, dw_b);
    k5_gemm<<<dim3(HWP/PT, CC/OT, NB), 256>>>(conv3_w, conv4_w, conv3_b, conv4_b);
    k6_redux<<<NB*CC, 256>>>();
    k7_latt<<<NB, CC>>>(la1_w, la_g, la_b, la_rm, la_rv, fh_w, fw_w);
    k8_final<<<NB*CC, 256>>>(out);
}

// round 2
// speedup vs baseline: 1.1928x; 1.1928x over previous
#include <cuda_runtime.h>
#include <cuda_bf16.h>

#define NB 16
#define CC 256
#define HWP 4096
#define OT 128
#define PT 64
#define KT 16
#define SWS 130
#define NELEM (NB*CC*HWP)

typedef unsigned long long u64;

// ---------------- scratch (static device allocations) ----------------
__device__ float g_g1[NELEM];
__device__ float g_XG[NELEM];
__device__ float g_xup[NELEM];
__device__ float g_base[NELEM];
__device__ float g_dw[NELEM];
__device__ float g_xL[NELEM];

__device__ float g_sum[NB*CC];
__device__ float g_sumsq[NB*CC];
__device__ float g_mean[NB*CC];
__device__ float g_cagate[NB*CC];
__device__ float g_sumxlow[NB*CC];
__device__ float g_gate[NB*CC];
__device__ float g_bninv[CC];
__device__ float g_bnsh[CC];
__device__ float g_gmu[NB*16];
__device__ float g_grstd[NB*16];
__device__ float g_s4g[NB*HWP];
__device__ float g_xh[NB*CC*64];
__device__ float g_xw[NB*CC*64];
__device__ float g_sh[NB*CC*64];
__device__ float g_sw[NB*CC*64];

__device__ __forceinline__ float sigm(float x){ return 1.0f/(1.0f+expf(-x)); }

__device__ __forceinline__ u64 pack_dup(float x){
    u64 r; asm("mov.b64 %0, {%1, %1};" : "=l"(r) : "f"(x)); return r;
}
__device__ __forceinline__ void ffma2(u64& d, u64 a, u64 b){
    asm("fma.rn.f32x2 %0, %1, %2, %0;" : "+l"(d) : "l"(a), "l"(b));
}
__device__ __forceinline__ float2 u2f(u64 v){
    float2 r; asm("mov.b64 {%0, %1}, %2;" : "=f"(r.x), "=f"(r.y) : "l"(v)); return r;
}

// ---------------- K0: zero the atomic accumulators ----------------
__global__ void k0_zero()
{
    int i = blockIdx.x*256 + threadIdx.x;   // grid covers 65536
    if (i < NB*CC){ g_sum[i]=0.f; g_sumsq[i]=0.f; }
    if (i < NB*HWP) g_s4g[i]=0.f;
}

// ---------------- K1: dual GEMM g1/g2 + XG + fused reductions (FFMA2) ----------------
__global__ __launch_bounds__(256) void k1_gemm(
    const float* __restrict__ x1, const float* __restrict__ x2,
    const float* __restrict__ w1, const float* __restrict__ w2,
    const float* __restrict__ b1, const float* __restrict__ b2,
    const float* __restrict__ w4g)
{
    __shared__ __align__(16) float sW1[KT*SWS];
    __shared__ __align__(16) float sW2[KT*SWS];
    __shared__ __align__(16) float sA1[KT*PT];
    __shared__ __align__(16) float sA2[KT*PT];
    __shared__ float sred[16][PT];

    const int tid = threadIdx.x;
    const int tx = tid & 15, ty = tid >> 4;
    const int pBase = blockIdx.x * PT;
    const int oBase = blockIdx.y * OT;
    const int n = blockIdx.z;

    const float* A1 = x1 + (size_t)n * CC * HWP;
    const float* A2 = x2 + (size_t)n * CC * HWP;

    u64 acc1[4][2][2], acc2[4][2][2];   // [i][e][jp], packed over pixel pair
    #pragma unroll
    for (int i=0;i<4;i++)
        #pragma unroll
        for (int e=0;e<2;e++)
            #pragma unroll
            for (int jp=0;jp<2;jp++){ acc1[i][e][jp]=0ull; acc2[i][e][jp]=0ull; }

    for (int k0 = 0; k0 < CC; k0 += KT){
        // stage weights transposed into [k][o]
        #pragma unroll
        for (int r=0;r<2;r++){
            int f = tid + 256*r;
            int oo = f >> 2;
            int kk = (f & 3) << 2;
            const float4 v1 = *(const float4*)(w1 + (size_t)(oBase+oo)*CC + k0 + kk);
            const float4 v2 = *(const float4*)(w2 + (size_t)(oBase+oo)*CC + k0 + kk);
            sW1[(kk+0)*SWS+oo]=v1.x; sW1[(kk+1)*SWS+oo]=v1.y; sW1[(kk+2)*SWS+oo]=v1.z; sW1[(kk+3)*SWS+oo]=v1.w;
            sW2[(kk+0)*SWS+oo]=v2.x; sW2[(kk+1)*SWS+oo]=v2.y; sW2[(kk+2)*SWS+oo]=v2.z; sW2[(kk+3)*SWS+oo]=v2.w;
        }
        {
            int kk = tid >> 4;
            int pp = (tid & 15) << 2;
            *(float4*)&sA1[kk*PT+pp] = *(const float4*)(A1 + (size_t)(k0+kk)*HWP + pBase + pp);
            *(float4*)&sA2[kk*PT+pp] = *(const float4*)(A2 + (size_t)(k0+kk)*HWP + pBase + pp);
        }
        __syncthreads();
        #pragma unroll
        for (int k=0;k<KT;k++){
            const float* wr1 = sW1 + k*SWS + ty*2;
            const float* wr2 = sW2 + k*SWS + ty*2;
            const float* ar1 = sA1 + k*PT + tx*2;
            const float* ar2 = sA2 + k*PT + tx*2;
            u64 a1a = *(const u64*)(ar1);
            u64 a1b = *(const u64*)(ar1 + 32);
            u64 a2a = *(const u64*)(ar2);
            u64 a2b = *(const u64*)(ar2 + 32);
            #pragma unroll
            for (int i=0;i<4;i++){
                float2 wp1 = *(const float2*)(wr1 + 32*i);
                float2 wp2 = *(const float2*)(wr2 + 32*i);
                u64 w10 = pack_dup(wp1.x), w11 = pack_dup(wp1.y);
                u64 w20 = pack_dup(wp2.x), w21 = pack_dup(wp2.y);
                ffma2(acc1[i][0][0], w10, a1a);
                ffma2(acc1[i][0][1], w10, a1b);
                ffma2(acc1[i][1][0], w11, a1a);
                ffma2(acc1[i][1][1], w11, a1b);
                ffma2(acc2[i][0][0], w20, a2a);
                ffma2(acc2[i][0][1], w20, a2b);
                ffma2(acc2[i][1][0], w21, a2a);
                ffma2(acc2[i][1][1], w21, a2b);
            }
        }
        __syncthreads();
    }

    // epilogue: biases, write g1/XG, fused reductions
    float sxp[2][2] = {{0.f,0.f},{0.f,0.f}};   // [jp][l] per-pixel partial of conv4g dot
    const size_t nb = (size_t)n * CC * HWP;
    #pragma unroll
    for (int i=0;i<4;i++){
        #pragma unroll
        for (int e=0;e<2;e++){
            int o = oBase + ty*2 + 32*i + e;
            float bb1 = b1[o], bb2 = b2[o];
            float wg  = w4g[o];
            float ssum = 0.f, ssq = 0.f;
            #pragma unroll
            for (int jp=0;jp<2;jp++){
                float2 v1 = u2f(acc1[i][e][jp]);
                float2 v2 = u2f(acc2[i][e][jp]);
                v1.x += bb1; v1.y += bb1;
                v2.x += bb2; v2.y += bb2;
                float2 xg = make_float2(v1.x+v2.x, v1.y+v2.y);
                size_t idx = nb + (size_t)o*HWP + pBase + tx*2 + 32*jp;
                *(float2*)(g_g1 + idx) = v1;
                *(float2*)(g_XG + idx) = xg;
                ssum += xg.x + xg.y;
                ssq  = fmaf(xg.x, xg.x, ssq);
                ssq  = fmaf(xg.y, xg.y, ssq);
                sxp[jp][0] = fmaf(wg, xg.x, sxp[jp][0]);
                sxp[jp][1] = fmaf(wg, xg.y, sxp[jp][1]);
            }
            #pragma unroll
            for (int d=8; d; d>>=1){
                ssum += __shfl_xor_sync(0xffffffffu, ssum, d);
                ssq  += __shfl_xor_sync(0xffffffffu, ssq,  d);
            }
            if (tx == 0){
                atomicAdd(&g_sum[n*CC+o],   ssum);
                atomicAdd(&g_sumsq[n*CC+o], ssq);
            }
        }
    }
    #pragma unroll
    for (int jp=0;jp<2;jp++){
        sred[ty][tx*2 + 32*jp + 0] = sxp[jp][0];
        sred[ty][tx*2 + 32*jp + 1] = sxp[jp][1];
    }
    __syncthreads();
    if (tid < PT){
        float s = 0.f;
        #pragma unroll
        for (int t=0;t<16;t++) s += sred[t][tid];
        atomicAdd(&g_s4g[n*HWP + pBase + tid], s);
    }
}

// ---------------- K2: per-(n,c) stats, channel-att conv1d, group mu/std ----------------
__global__ __launch_bounds__(256) void k2_stats(
    const float* __restrict__ bn_g, const float* __restrict__ bn_b,
    const float* __restrict__ bn_rm, const float* __restrict__ bn_rv,
    const float* __restrict__ ca_w)
{
    const int n = blockIdx.x;
    const int c = threadIdx.x;
    __shared__ float sm[CC];
    float mean = g_sum[n*CC+c] * (1.0f/HWP);
    sm[c] = mean;
    g_mean[n*CC+c] = mean;
    if (n == 0){
        float inv = bn_g[c] * rsqrtf(bn_rv[c] + 1e-5f);
        g_bninv[c] = inv;
        g_bnsh[c]  = bn_b[c] - bn_rm[c]*inv;
    }
    __syncthreads();
    float y = 0.f;
    #pragma unroll
    for (int k=0;k<5;k++){
        int cc2 = c + k - 2;
        if (cc2 >= 0 && cc2 < CC) y = fmaf(sm[cc2], ca_w[k], y);
    }
    g_cagate[n*CC+c] = sigm(y);
    if ((c & 15) == 0){
        float s=0.f, q=0.f;
        for (int t=0;t<16;t++){ s += g_sum[n*CC+c+t]; q += g_sumsq[n*CC+c+t]; }
        const float cnt = 16.0f*HWP;
        float mu  = s / cnt;
        float var = (q - cnt*mu*mu) / (cnt - 1.0f);
        var = fmaxf(var, 0.0f);
        float sd = sqrtf(var);
        g_gmu[n*16 + (c>>4)]   = mu;
        g_grstd[n*16 + (c>>4)] = 1.0f/(sd + 1e-10f);
    }
}

// ---------------- K34: fused masks/x_up/base + depthwise 3x3 on x_low ----------------
__global__ __launch_bounds__(256) void k_lowdw(
    const float* __restrict__ gamma, const float* __restrict__ beta,
    const float* __restrict__ b4g,
    const float* __restrict__ dw_w, const float* __restrict__ dw_b)
{
    const int nc = blockIdx.x;
    const int n = nc >> 8, c = nc & (CC-1);
    const size_t off = (size_t)nc * HWP;
    const float mean = g_mean[nc];
    const float inv = g_bninv[c], shv = g_bnsh[c];
    const int g = c >> 4;
    const float mu = g_gmu[n*16+g], rstd = g_grstd[n*16+g];
    const float gm = gamma[c], bt = beta[c];
    const float cag = g_cagate[nc];
    const float b4 = b4g[0];

    __shared__ float tile[66*66];
    __shared__ float wred[8];
    const int tid = threadIdx.x;

    float lowsum = 0.f;
    for (int i = tid; i < 66*66; i += 256){
        int hh = i/66 - 1, ww = i%66 - 1;
        float xl = 0.f;
        if (hh >= 0 && hh < 64 && ww >= 0 && ww < 64){
            int p = hh*64 + ww;
            float xg  = g_XG[off + p];
            float g1v = g_g1[off + p];
            float g2v = xg - g1v;
            float fu = ((mean >= fmaf(g1v, inv, shv)) ? 1.f : 0.f)
                     + ((mean >= fmaf(g2v, inv, shv)) ? 1.f : 0.f);
            xl = xg * (2.0f - fu);
            float xu = xg * fu;
            float Xs = xg * sigm(g_s4g[n*HWP + p] + b4);
            g_xup[off + p]  = xu;
            g_base[off + p] = fmaf((Xs - mu)*rstd, gm, bt) + xg*cag;
            lowsum += xl;
        }
        tile[i] = xl;
    }
    #pragma unroll
    for (int d=16; d; d>>=1) lowsum += __shfl_xor_sync(0xffffffffu, lowsum, d);
    if ((tid & 31) == 0) wred[tid >> 5] = lowsum;
    __syncthreads();
    if (tid == 0){
        float s = 0.f;
        #pragma unroll
        for (int i=0;i<8;i++) s += wred[i];
        g_sumxlow[nc] = s;
    }

    float wc[9];
    #pragma unroll
    for (int k=0;k<9;k++) wc[k] = dw_w[c*9+k];
    const float bb = dw_b[c];
    for (int p = tid; p < HWP; p += 256){
        int h = p >> 6, w = p & 63;
        float acc = bb;
        #pragma unroll
        for (int i=0;i<3;i++)
            #pragma unroll
            for (int j=0;j<3;j++)
                acc = fmaf(tile[(h+i)*66 + (w+j)], wc[i*3+j], acc);
        g_dw[off+p] = acc;
    }
}

// ---------------- K3.5: gate = softmax(relu(mean(x_low) @ gate_w.T + b)) ----------------
__global__ __launch_bounds__(256) void k_gate(
    const float* __restrict__ gate_w, const float* __restrict__ gate_b)
{
    const int n = blockIdx.x;
    const int o = threadIdx.x;
    __shared__ float mv[CC];
    __shared__ float red[CC];
    mv[o] = g_sumxlow[n*CC+o] * (1.0f/HWP);
    __syncthreads();
    float acc = gate_b[o];
    #pragma unroll 8
    for (int c2=0;c2<CC;c2++) acc = fmaf(mv[c2], gate_w[(size_t)o*CC + c2], acc);
    acc = fmaxf(acc, 0.0f);
    red[o] = acc; __syncthreads();
    for (int s=128; s; s>>=1){ if (o < s) red[o] = fmaxf(red[o], red[o+s]); __syncthreads(); }
    float m = red[0];
    __syncthreads();
    float e = expf(acc - m);
    red[o] = e; __syncthreads();
    for (int s=128; s; s>>=1){ if (o < s) red[o] += red[o+s]; __syncthreads(); }
    g_gate[n*CC+o] = e / red[0];
}

// ---------------- K5: dual GEMM xL = gate*conv3(dw) + conv4(x_up) + base (FFMA2) ----------------
__global__ __launch_bounds__(256) void k5_gemm(
    const float* __restrict__ w3, const float* __restrict__ w4,
    const float* __restrict__ b3, const float* __restrict__ b4)
{
    __shared__ __align__(16) float sW1[KT*SWS];
    __shared__ __align__(16) float sW2[KT*SWS];
    __shared__ __align__(16) float sA1[KT*PT];
    __shared__ __align__(16) float sA2[KT*PT];

    const int tid = threadIdx.x;
    const int tx = tid & 15, ty = tid >> 4;
    const int pBase = blockIdx.x * PT;
    const int oBase = blockIdx.y * OT;
    const int n = blockIdx.z;

    const float* A1 = g_dw  + (size_t)n * CC * HWP;
    const float* A2 = g_xup + (size_t)n * CC * HWP;

    u64 acc1[4][2][2], acc2[4][2][2];
    #pragma unroll
    for (int i=0;i<4;i++)
        #pragma unroll
        for (int e=0;e<2;e++)
            #pragma unroll
            for (int jp=0;jp<2;jp++){ acc1[i][e][jp]=0ull; acc2[i][e][jp]=0ull; }

    for (int k0 = 0; k0 < CC; k0 += KT){
        #pragma unroll
        for (int r=0;r<2;r++){
            int f = tid + 256*r;
            int oo = f >> 2;
            int kk = (f & 3) << 2;
            const float4 v1 = *(const float4*)(w3 + (size_t)(oBase+oo)*CC + k0 + kk);
            const float4 v2 = *(const float4*)(w4 + (size_t)(oBase+oo)*CC + k0 + kk);
            sW1[(kk+0)*SWS+oo]=v1.x; sW1[(kk+1)*SWS+oo]=v1.y; sW1[(kk+2)*SWS+oo]=v1.z; sW1[(kk+3)*SWS+oo]=v1.w;
            sW2[(kk+0)*SWS+oo]=v2.x; sW2[(kk+1)*SWS+oo]=v2.y; sW2[(kk+2)*SWS+oo]=v2.z; sW2[(kk+3)*SWS+oo]=v2.w;
        }
        {
            int kk = tid >> 4;
            int pp = (tid & 15) << 2;
            *(float4*)&sA1[kk*PT+pp] = *(const float4*)(A1 + (size_t)(k0+kk)*HWP + pBase + pp);
            *(float4*)&sA2[kk*PT+pp] = *(const float4*)(A2 + (size_t)(k0+kk)*HWP + pBase + pp);
        }
        __syncthreads();
        #pragma unroll
        for (int k=0;k<KT;k++){
            const float* wr1 = sW1 + k*SWS + ty*2;
            const float* wr2 = sW2 + k*SWS + ty*2;
            const float* ar1 = sA1 + k*PT + tx*2;
            const float* ar2 = sA2 + k*PT + tx*2;
            u64 a1a = *(const u64*)(ar1);
            u64 a1b = *(const u64*)(ar1 + 32);
            u64 a2a = *(const u64*)(ar2);
            u64 a2b = *(const u64*)(ar2 + 32);
            #pragma unroll
            for (int i=0;i<4;i++){
                float2 wp1 = *(const float2*)(wr1 + 32*i);
                float2 wp2 = *(const float2*)(wr2 + 32*i);
                u64 w10 = pack_dup(wp1.x), w11 = pack_dup(wp1.y);
                u64 w20 = pack_dup(wp2.x), w21 = pack_dup(wp2.y);
                ffma2(acc1[i][0][0], w10, a1a);
                ffma2(acc1[i][0][1], w10, a1b);
                ffma2(acc1[i][1][0], w11, a1a);
                ffma2(acc1[i][1][1], w11, a1b);
                ffma2(acc2[i][0][0], w20, a2a);
                ffma2(acc2[i][0][1], w20, a2b);
                ffma2(acc2[i][1][0], w21, a2a);
                ffma2(acc2[i][1][1], w21, a2b);
            }
        }
        __syncthreads();
    }

    const size_t nb = (size_t)n * CC * HWP;
    #pragma unroll
    for (int i=0;i<4;i++){
        #pragma unroll
        for (int e=0;e<2;e++){
            int o = oBase + ty*2 + 32*i + e;
            float bb3 = b3[o], bb4 = b4[o];
            float gt = g_gate[n*CC+o];
            #pragma unroll
            for (int jp=0;jp<2;jp++){
                size_t idx = nb + (size_t)o*HWP + pBase + tx*2 + 32*jp;
                float2 v1 = u2f(acc1[i][e][jp]);
                float2 v2 = u2f(acc2[i][e][jp]);
                float2 bsv = *(const float2*)(g_base + idx);
                float2 out;
                out.x = (v1.x + bb3)*gt + (v2.x + bb4) + bsv.x;
                out.y = (v1.y + bb3)*gt + (v2.y + bb4) + bsv.y;
                *(float2*)(g_xL + idx) = out;
            }
        }
    }
}

// ---------------- K6: row/col means of xL ----------------
__global__ __launch_bounds__(256) void k6_redux()
{
    const int nc = blockIdx.x;
    const size_t off = (size_t)nc * HWP;
    __shared__ float rsum[64];
    __shared__ float cpart[4][64];
    const int tid = threadIdx.x, l = tid & 31, wp = tid >> 5;
    if (tid < 64) rsum[tid] = 0.f;
    __syncthreads();
    const int w = (wp & 1)*32 + l;
    const int hq = wp >> 1;
    float colacc = 0.f;
    for (int r=0;r<16;r++){
        int h = hq*16 + r;
        float v = g_xL[off + h*64 + w];
        colacc += v;
        float s = v;
        #pragma unroll
        for (int d=16; d; d>>=1) s += __shfl_xor_sync(0xffffffffu, s, d);
        if (l == 0) atomicAdd(&rsum[h], s);
    }
    cpart[hq][w] = colacc;
    __syncthreads();
    if (tid < 64){
        g_xw[(size_t)nc*64 + tid] =
            (cpart[0][tid]+cpart[1][tid]+cpart[2][tid]+cpart[3][tid]) * (1.0f/64.0f);
        g_xh[(size_t)nc*64 + tid] = rsum[tid] * (1.0f/64.0f);
    }
}

// ---------------- K7: coordinate attention (tiny GEMMs) ----------------
__global__ __launch_bounds__(256) void k7_latt(
    const float* __restrict__ la1_w,
    const float* __restrict__ la_g, const float* __restrict__ la_b,
    const float* __restrict__ la_rm, const float* __restrict__ la_rv,
    const float* __restrict__ fh_w, const float* __restrict__ fw_w)
{
    const int n = blockIdx.x;
    __shared__ float syc[16][128];
    const int tid = threadIdx.x;
    for (int e = tid; e < 16*128; e += 256){
        int m = e >> 7, l = e & 127;
        const float* src = (l < 64) ? (g_xh + (size_t)n*CC*64 + l)
                                    : (g_xw + (size_t)n*CC*64 + (l - 64));
        float acc = 0.f;
        #pragma unroll 8
        for (int c2=0;c2<CC;c2++) acc = fmaf(la1_w[m*CC + c2], src[(size_t)c2*64], acc);
        float inv = la_g[m] * rsqrtf(la_rv[m] + 1e-5f);
        float v = acc*inv + (la_b[m] - la_rm[m]*inv);
        syc[m][l] = fmaxf(v, 0.f);
    }
    __syncthreads();
    const int c = tid;
    for (int pos=0; pos<64; pos++){
        float sh = 0.f, sw = 0.f;
        #pragma unroll
        for (int m=0;m<16;m++){
            sh = fmaf(fh_w[c*16+m], syc[m][pos],      sh);
            sw = fmaf(fw_w[c*16+m], syc[m][64+pos],   sw);
        }
        g_sh[((size_t)n*CC + c)*64 + pos] = sigm(sh);
        g_sw[((size_t)n*CC + c)*64 + pos] = sigm(sw);
    }
}

// ---------------- K8: final out = xL * sh(h) * sw(w) ----------------
__global__ __launch_bounds__(256) void k8_final(float* __restrict__ out)
{
    const int nc = blockIdx.x;
    __shared__ float shv[64], swv[64];
    const int tid = threadIdx.x;
    if (tid < 64) shv[tid] = g_sh[(size_t)nc*64 + tid];
    else if (tid < 128) swv[tid-64] = g_sw[(size_t)nc*64 + (tid-64)];
    __syncthreads();
    const size_t off = (size_t)nc * HWP;
    for (int f = tid; f < 1024; f += 256){
        int p = f*4;
        int h = p >> 6, w = p & 63;
        float4 v = *(const float4*)(g_xL + off + p);
        float a = shv[h];
        v.x *= a*swv[w+0]; v.y *= a*swv[w+1]; v.z *= a*swv[w+2]; v.w *= a*swv[w+3];
        *(float4*)(out + off + p) = v;
    }
}

// ---------------- launch ----------------
extern "C" void kernel_launch(void* const* d_in, const int* in_sizes, int n_in,
                              void* d_out, int out_size)
{
    const float* x1      = (const float*)d_in[0];
    const float* x2      = (const float*)d_in[1];
    const float* conv1_w = (const float*)d_in[2];
    const float* conv1_b = (const float*)d_in[3];
    const float* conv2_w = (const float*)d_in[4];
    const float* conv2_b = (const float*)d_in[5];
    const float* conv3_w = (const float*)d_in[6];
    const float* conv3_b = (const float*)d_in[7];
    const float* conv4_w = (const float*)d_in[8];
    const float* conv4_b = (const float*)d_in[9];
    const float* conv4g_w= (const float*)d_in[10];
    const float* conv4g_b= (const float*)d_in[11];
    const float* bn_g    = (const float*)d_in[12];
    const float* bn_b    = (const float*)d_in[13];
    const float* bn_rm   = (const float*)d_in[14];
    const float* bn_rv   = (const float*)d_in[15];
    const float* gamma   = (const float*)d_in[16];
    const float* beta    = (const float*)d_in[17];
    const float* gate_w  = (const float*)d_in[18];
    const float* gate_b  = (const float*)d_in[19];
    const float* dw_w    = (const float*)d_in[20];
    const float* dw_b    = (const float*)d_in[21];
    // d_in[22], d_in[23]: interact_w / interact_b — dead code (softmax over size-1 axis == 1)
    const float* ca_w    = (const float*)d_in[24];
    const float* la1_w   = (const float*)d_in[25];
    const float* la_g    = (const float*)d_in[26];
    const float* la_b    = (const float*)d_in[27];
    const float* la_rm   = (const float*)d_in[28];
    const float* la_rv   = (const float*)d_in[29];
    const float* fh_w    = (const float*)d_in[30];
    const float* fw_w    = (const float*)d_in[31];
    float* out = (float*)d_out;

    k0_zero<<<256, 256>>>();
    k1_gemm<<<dim3(HWP/PT, CC/OT, NB), 256>>>(x1, x2, conv1_w, conv2_w, conv1_b, conv2_b, conv4g_w);
    k2_stats<<<NB, CC>>>(bn_g, bn_b, bn_rm, bn_rv, ca_w);
    k_lowdw<<<NB*CC, 256>>>(gamma, beta, conv4g_b, dw_w, dw_b);
    k_gate<<<NB, CC>>>(gate_w, gate_b);
    k5_gemm<<<dim3(HWP/PT, CC/OT, NB), 256>>>(conv3_w, conv4_w, conv3_b, conv4_b);
    k6_redux<<<NB*CC, 256>>>();
    k7_latt<<<NB, CC>>>(la1_w, la_g, la_b, la_rm, la_rv, fh_w, fw_w);
    k8_final<<<NB*CC, 256>>>(out);
}